// round 2
// baseline (speedup 1.0000x reference)
#include <cuda_runtime.h>
#include <math.h>

#define W 1024
#define H 1024
#define NB 4
#define NPIX (NB * W * H)

#define TS 128                 // hysteresis tile
#define TG (W / TS)            // 8
#define NT (NB * TG * TG)      // 256 tiles
#define NPASS 16

// ---------------- device scratch (no runtime allocation) ----------------
__device__ unsigned char g_state[NPIX];   // 0 none, 1 weak, 2 strong
__device__ int g_changed[NPASS];

__constant__ int c_dy[8] = {0, -1, -1, -1, 0, 1, 1, 1};
__constant__ int c_dx[8] = {1,  1,  0, -1, -1, -1, 0, 1};

__device__ __forceinline__ int reflect1024(int t) {
    t = (t < 0) ? -t : t;
    return (t > 1023) ? (2046 - t) : t;
}
__device__ __forceinline__ int clamp1024(int t) {
    return (t < 0) ? 0 : ((t > 1023) ? 1023 : t);
}

// =====================================================================
// Kernel A: gray -> 5x5 gaussian (direct, row-major FMA) -> sobel ->
//           magnitude -> NMS -> double threshold. 32x32 tile, halo 4.
// =====================================================================
__global__ __launch_bounds__(256) void canny_main(const float* __restrict__ in,
                                                  float* __restrict__ magout)
{
    __shared__ float Sg[40][41];    // gray, raw coords [y0-4, y0+35], reflect-mapped
    __shared__ float Sb[36][37];    // blurred at clamped (edge-pad) coords [y0-2, y0+33]
    __shared__ float Smag[34][35];  // magnitude (0 outside image) [y0-1, y0+32]
    __shared__ float Sgx[34][35];
    __shared__ float Sgy[34][35];

    const int tid = threadIdx.x;
    const int b  = blockIdx.z;
    const int y0 = blockIdx.y << 5;
    const int x0 = blockIdx.x << 5;
    const float* pr = in + (size_t)b * 3 * W * H;

    if (b == 0 && blockIdx.x == 0 && blockIdx.y == 0 && tid < NPASS)
        g_changed[tid] = 0;

    // gaussian weights exactly as numpy builds them (f32 throughout)
    const float E0 = 0.13533528323661270231f;   // exp(-2) correctly rounded
    const float E1 = 0.60653065971263342360f;   // exp(-0.5)
    const float gs = __fadd_rn(__fadd_rn(__fadd_rn(__fadd_rn(E0, E1), 1.0f), E1), E0);
    float g1d[5];
    g1d[0] = __fdiv_rn(E0, gs);
    g1d[1] = __fdiv_rn(E1, gs);
    g1d[2] = __fdiv_rn(1.0f, gs);
    g1d[3] = g1d[1];
    g1d[4] = g1d[0];

    // ---- gray with reflect padding ----
    for (int k = tid; k < 40 * 40; k += 256) {
        int j = k / 40, i = k - j * 40;
        int ry = reflect1024(y0 - 4 + j);
        int rx = reflect1024(x0 - 4 + i);
        int o = ry * W + rx;
        float r = pr[o], g = pr[o + W * H], bl = pr[o + 2 * W * H];
        Sg[j][i] = __fadd_rn(__fadd_rn(__fmul_rn(0.299f, r), __fmul_rn(0.587f, g)),
                             __fmul_rn(0.114f, bl));
    }
    __syncthreads();

    // ---- direct 5x5 gaussian at clamped (edge-pad) centers ----
    for (int k = tid; k < 36 * 36; k += 256) {
        int j = k / 36, i = k - j * 36;
        int sj = clamp1024(y0 - 2 + j) - y0 + 4;   // Sg row of center, in [2,37]
        int si = clamp1024(x0 - 2 + i) - x0 + 4;
        float acc = 0.0f;
#pragma unroll
        for (int r = 0; r < 5; ++r) {
#pragma unroll
            for (int c = 0; c < 5; ++c) {
                acc = fmaf(__fmul_rn(g1d[r], g1d[c]), Sg[sj - 2 + r][si - 2 + c], acc);
            }
        }
        Sb[j][i] = acc;
    }
    __syncthreads();

    // ---- sobel + magnitude over [y0-1, y0+32] (zero outside image for NMS) ----
    for (int k = tid; k < 34 * 34; k += 256) {
        int j = k / 34, i = k - j * 34;
        float a00 = Sb[j][i],     a01 = Sb[j][i + 1],     a02 = Sb[j][i + 2];
        float a10 = Sb[j + 1][i],                         a12 = Sb[j + 1][i + 2];
        float a20 = Sb[j + 2][i], a21 = Sb[j + 2][i + 1], a22 = Sb[j + 2][i + 2];
        // row-major sequential sums; all products exact (weights +-1,+-2)
        float gx = __fadd_rn(__fadd_rn(__fadd_rn(__fadd_rn(__fadd_rn(
                     -a00, a02), __fmul_rn(-2.0f, a10)), __fmul_rn(2.0f, a12)), -a20), a22);
        float gy = __fadd_rn(__fadd_rn(__fadd_rn(__fadd_rn(__fadd_rn(
                     -a00, __fmul_rn(-2.0f, a01)), -a02), a20), __fmul_rn(2.0f, a21)), a22);
        float s = __fadd_rn(__fadd_rn(__fmul_rn(gx, gx), __fmul_rn(gy, gy)), 1e-6f);
        float m = __fsqrt_rn(s);
        int yy = y0 - 1 + j, xx = x0 - 1 + i;
        bool inb = ((unsigned)yy < 1024u) && ((unsigned)xx < 1024u);
        Smag[j][i] = inb ? m : 0.0f;
        Sgx[j][i] = gx;
        Sgy[j][i] = gy;
    }
    __syncthreads();

    // ---- NMS + double threshold ----
    for (int k = tid; k < 1024; k += 256) {
        int j = k >> 5, i = k & 31;
        float m  = Smag[j + 1][i + 1];
        float gx = Sgx[j + 1][i + 1];
        float gy = Sgy[j + 1][i + 1];
        float ang = __fmul_rn(atan2f(gy, gx), 57.29577951308232087680f);
        int q = (int)rintf(__fdiv_rn(ang, 45.0f));   // in [-4,4], half-even like jnp.round
        int pos = q & 7;
        int neg = (q + 4) & 7;
        float np_ = Smag[j + 1 + c_dy[pos]][i + 1 + c_dx[pos]];
        float nn_ = Smag[j + 1 + c_dy[neg]][i + 1 + c_dx[neg]];
        float mo = (fminf(__fadd_rn(m, -np_), __fadd_rn(m, -nn_)) > 0.0f) ? m : 0.0f;
        int o = (b * H + y0 + j) * W + x0 + i;
        magout[o] = mo;
        g_state[o] = (mo > 0.2f) ? (unsigned char)2
                   : ((mo > 0.1f) ? (unsigned char)1 : (unsigned char)0);
    }
}

// =====================================================================
// Kernel B: one hysteresis sweep pass. 128x128 tile to local fixed point.
// Early-exits if previous pass changed nothing. Promotions are monotone
// (1->2 only) so concurrent halo reads are benign; the global fixed
// point is unique => deterministic.
// =====================================================================
__global__ __launch_bounds__(256) void hyst_pass(int pass)
{
    if (pass > 0 && g_changed[pass - 1] == 0) return;

    __shared__ unsigned char s[TS + 2][TS + 4];
    __shared__ int s_flag;
    const int tid = threadIdx.x;
    const int t = blockIdx.x;
    const int b  = t >> 6;            // /64
    const int tr = (t >> 3) & 7;
    const int tc = t & 7;
    const int y0 = tr * TS, x0 = tc * TS;
    unsigned char* st = g_state + (size_t)b * (W * H);

    // load (TS+2)x(TS+2) halo tile
    for (int k = tid; k < (TS + 2) * (TS + 2); k += 256) {
        int j = k / (TS + 2), i = k - j * (TS + 2);
        int y = y0 + j - 1, x = x0 + i - 1;
        unsigned char v = 0;
        if ((unsigned)y < 1024u && (unsigned)x < 1024u) v = st[y * W + x];
        s[j][i] = v;
    }
    __syncthreads();

    int any = 0;
    const int tx = (tid & 31) * 4 + 1;
    const int tyb = (tid >> 5) + 1;
    for (;;) {
        if (tid == 0) s_flag = 0;
        __syncthreads();
        int ch = 0;
        for (int rr = 0; rr < TS / 8; ++rr) {
            int j = tyb + rr * 8;
#pragma unroll
            for (int c4 = 0; c4 < 4; ++c4) {
                int i = tx + c4;
                if (s[j][i] == 1) {
                    int n = (s[j-1][i-1] == 2) | (s[j-1][i] == 2) | (s[j-1][i+1] == 2)
                          | (s[j  ][i-1] == 2) |                    (s[j  ][i+1] == 2)
                          | (s[j+1][i-1] == 2) | (s[j+1][i] == 2) | (s[j+1][i+1] == 2);
                    if (n) { s[j][i] = 2; ch = 1; }
                }
            }
        }
        if (ch) { s_flag = 1; any = 1; }
        __syncthreads();
        if (!s_flag) break;
    }

    if (__syncthreads_or(any)) {
        for (int k = tid; k < TS * TS; k += 256) {
            int j = k >> 7, i = k & 127;
            st[(y0 + j) * W + x0 + i] = s[j + 1][i + 1];
        }
        if (tid == 0) g_changed[pass] = 1;
    }
}

// =====================================================================
// Kernel C: edges = 1.0 where strong else 0.0 (vectorized)
// =====================================================================
__global__ __launch_bounds__(256) void edges_final(float* __restrict__ e)
{
    int i = blockIdx.x * 256 + threadIdx.x;     // over NPIX/4
    uchar4 v = ((const uchar4*)g_state)[i];
    float4 f;
    f.x = (v.x == 2) ? 1.0f : 0.0f;
    f.y = (v.y == 2) ? 1.0f : 0.0f;
    f.z = (v.z == 2) ? 1.0f : 0.0f;
    f.w = (v.w == 2) ? 1.0f : 0.0f;
    ((float4*)e)[i] = f;
}

// =====================================================================
extern "C" void kernel_launch(void* const* d_in, const int* in_sizes, int n_in,
                              void* d_out, int out_size)
{
    (void)in_sizes; (void)n_in; (void)out_size;
    const float* x = (const float*)d_in[0];
    float* out = (float*)d_out;          // magnitude (4,1,1024,1024)
    float* edges = out + (size_t)NPIX;   // edges     (4,1,1024,1024)

    dim3 grid(32, 32, NB);
    canny_main<<<grid, 256>>>(x, out);

    for (int p = 0; p < NPASS; ++p)
        hyst_pass<<<NT, 256>>>(p);

    edges_final<<<NPIX / 1024, 256>>>(edges);
}

// round 3
// speedup vs baseline: 1.4240x; 1.4240x over previous
#include <cuda_runtime.h>
#include <math.h>

#define W 1024
#define H 1024
#define NB 4
#define NPIX (NB * W * H)

#define NPASS 16
#define RT 64                       // hysteresis rows per tile
#define HBLOCKS (NB * H / RT)       // 64 blocks
#define WPR 16                      // u64 words per row (1024 bits)

// ---------------- device scratch (no runtime allocation) ----------------
__device__ unsigned long long g_fill[NB * H * WPR];    // weak-or-strong bits
__device__ unsigned long long g_strong[NB * H * WPR];  // strong bits (grows)
__device__ int g_changed[NPASS];

__constant__ int c_dy[8] = {0, -1, -1, -1, 0, 1, 1, 1};
__constant__ int c_dx[8] = {1,  1,  0, -1, -1, -1, 0, 1};

__device__ __forceinline__ int reflect1024(int t) {
    t = (t < 0) ? -t : t;
    return (t > 1023) ? (2046 - t) : t;
}
__device__ __forceinline__ int clamp1024(int t) {
    return (t < 0) ? 0 : ((t > 1023) ? 1023 : t);
}

// =====================================================================
// Kernel A: gray -> 5x5 gaussian (direct, row-major FMA) -> sobel ->
//           magnitude -> NMS -> double threshold (emitted as bit planes).
//           32x32 tile, halo 4. All arithmetic identical to R2.
// =====================================================================
__global__ __launch_bounds__(256) void canny_main(const float* __restrict__ in,
                                                  float* __restrict__ magout)
{
    __shared__ float4 SgQ[40][11];   // gray, pitch 44 floats (16B aligned rows)
    __shared__ float Sb[36][37];     // blurred at clamped (edge-pad) coords
    __shared__ float Smag[34][35];   // magnitude (0 outside image)
    __shared__ float Sgx[34][35];
    __shared__ float Sgy[34][35];
    float* Sg = (float*)SgQ;         // Sg[row*44 + col]

    const int tid = threadIdx.x;
    const int b  = blockIdx.z;
    const int y0 = blockIdx.y << 5;
    const int x0 = blockIdx.x << 5;
    const float* pr = in + (size_t)b * 3 * W * H;

    if (b == 0 && blockIdx.x == 0 && blockIdx.y == 0 && tid < NPASS)
        g_changed[tid] = 0;

    // gaussian weights exactly as numpy builds them (f32 throughout)
    const float E0 = 0.13533528323661270231f;   // exp(-2) correctly rounded
    const float E1 = 0.60653065971263342360f;   // exp(-0.5)
    const float gs = __fadd_rn(__fadd_rn(__fadd_rn(__fadd_rn(E0, E1), 1.0f), E1), E0);
    float g1d[5];
    g1d[0] = __fdiv_rn(E0, gs);
    g1d[1] = __fdiv_rn(E1, gs);
    g1d[2] = __fdiv_rn(1.0f, gs);
    g1d[3] = g1d[1];
    g1d[4] = g1d[0];
    float g2d[5][5];
#pragma unroll
    for (int r = 0; r < 5; ++r)
#pragma unroll
        for (int c = 0; c < 5; ++c)
            g2d[r][c] = __fmul_rn(g1d[r], g1d[c]);

    // ---- gray with reflect padding ----
    for (int k = tid; k < 40 * 40; k += 256) {
        int j = k / 40, i = k - j * 40;
        int ry = reflect1024(y0 - 4 + j);
        int rx = reflect1024(x0 - 4 + i);
        int o = ry * W + rx;
        float r = pr[o], g = pr[o + W * H], bl = pr[o + 2 * W * H];
        Sg[j * 44 + i] = __fadd_rn(__fadd_rn(__fmul_rn(0.299f, r), __fmul_rn(0.587f, g)),
                                   __fmul_rn(0.114f, bl));
    }
    __syncthreads();

    // ---- direct 5x5 gaussian at clamped (edge-pad) centers ----
    const bool interior = (blockIdx.x >= 1) && (blockIdx.x <= 30) &&
                          (blockIdx.y >= 1) && (blockIdx.y <= 30);
    if (interior) {
        // no clamping possible: center row/col index = j+2 / i+2 directly.
        // vectorized: 4 adjacent column outputs share two float4 row loads.
        for (int k = tid; k < 36 * 9; k += 256) {
            int j = k / 9, q = k - j * 9;           // output cols 4q..4q+3
            float acc0 = 0.f, acc1 = 0.f, acc2 = 0.f, acc3 = 0.f;
#pragma unroll
            for (int r = 0; r < 5; ++r) {
                float4 A = SgQ[j + r][q];
                float4 B = SgQ[j + r][q + 1];
                float v[8] = {A.x, A.y, A.z, A.w, B.x, B.y, B.z, B.w};
#pragma unroll
                for (int c = 0; c < 5; ++c) {
                    acc0 = fmaf(g2d[r][c], v[c],     acc0);
                    acc1 = fmaf(g2d[r][c], v[c + 1], acc1);
                    acc2 = fmaf(g2d[r][c], v[c + 2], acc2);
                    acc3 = fmaf(g2d[r][c], v[c + 3], acc3);
                }
            }
            Sb[j][4 * q + 0] = acc0;
            Sb[j][4 * q + 1] = acc1;
            Sb[j][4 * q + 2] = acc2;
            Sb[j][4 * q + 3] = acc3;
        }
    } else {
        for (int k = tid; k < 36 * 36; k += 256) {
            int j = k / 36, i = k - j * 36;
            int sj = clamp1024(y0 - 2 + j) - y0 + 4;   // center row in Sg, [2,37]
            int si = clamp1024(x0 - 2 + i) - x0 + 4;
            float acc = 0.0f;
#pragma unroll
            for (int r = 0; r < 5; ++r)
#pragma unroll
                for (int c = 0; c < 5; ++c)
                    acc = fmaf(g2d[r][c], Sg[(sj - 2 + r) * 44 + (si - 2 + c)], acc);
            Sb[j][i] = acc;
        }
    }
    __syncthreads();

    // ---- sobel + magnitude over [y0-1, y0+32] (zero outside image for NMS) ----
    for (int k = tid; k < 34 * 34; k += 256) {
        int j = k / 34, i = k - j * 34;
        float a00 = Sb[j][i],     a01 = Sb[j][i + 1],     a02 = Sb[j][i + 2];
        float a10 = Sb[j + 1][i],                         a12 = Sb[j + 1][i + 2];
        float a20 = Sb[j + 2][i], a21 = Sb[j + 2][i + 1], a22 = Sb[j + 2][i + 2];
        float gx = __fadd_rn(__fadd_rn(__fadd_rn(__fadd_rn(__fadd_rn(
                     -a00, a02), __fmul_rn(-2.0f, a10)), __fmul_rn(2.0f, a12)), -a20), a22);
        float gy = __fadd_rn(__fadd_rn(__fadd_rn(__fadd_rn(__fadd_rn(
                     -a00, __fmul_rn(-2.0f, a01)), -a02), a20), __fmul_rn(2.0f, a21)), a22);
        float s = __fadd_rn(__fadd_rn(__fmul_rn(gx, gx), __fmul_rn(gy, gy)), 1e-6f);
        float m = __fsqrt_rn(s);
        int yy = y0 - 1 + j, xx = x0 - 1 + i;
        bool inb = ((unsigned)yy < 1024u) && ((unsigned)xx < 1024u);
        Smag[j][i] = inb ? m : 0.0f;
        Sgx[j][i] = gx;
        Sgy[j][i] = gy;
    }
    __syncthreads();

    // ---- NMS + double threshold; emit magnitude + fill/strong bit planes ----
    unsigned* fillp   = (unsigned*)g_fill;
    unsigned* strongp = (unsigned*)g_strong;
    for (int k = tid; k < 1024; k += 256) {
        int j = k >> 5, i = k & 31;                 // i == lane, j uniform per warp
        float m  = Smag[j + 1][i + 1];
        float gx = Sgx[j + 1][i + 1];
        float gy = Sgy[j + 1][i + 1];
        float ang = __fmul_rn(atan2f(gy, gx), 57.29577951308232087680f);
        int q = (int)rintf(__fdiv_rn(ang, 45.0f));   // [-4,4], half-even
        int pos = q & 7;
        int neg = (q + 4) & 7;
        float np_ = Smag[j + 1 + c_dy[pos]][i + 1 + c_dx[pos]];
        float nn_ = Smag[j + 1 + c_dy[neg]][i + 1 + c_dx[neg]];
        float mo = (fminf(__fadd_rn(m, -np_), __fadd_rn(m, -nn_)) > 0.0f) ? m : 0.0f;
        int y = y0 + j;
        magout[(b * H + y) * W + x0 + i] = mo;
        unsigned fm = __ballot_sync(0xffffffffu, mo > 0.1f);
        unsigned sm = __ballot_sync(0xffffffffu, mo > 0.2f);
        if (i == 0) {
            int wi = (b * H + y) * (2 * WPR) + (x0 >> 5);
            fillp[wi] = fm;
            strongp[wi] = sm;
        }
    }
}

// =====================================================================
// Kernel B: one bit-parallel hysteresis pass. 64 rows x 1024 cols per
// block; relax to local fixed point in shared (u64 words, shift/OR
// dilation). Monotone growth => unique fixed point => deterministic.
// =====================================================================
__global__ __launch_bounds__(256) void hyst_pass(int pass)
{
    if (pass > 0 && g_changed[pass - 1] == 0) return;

    __shared__ unsigned long long sS[RT + 2][WPR + 1];
    __shared__ unsigned long long sF[RT + 2][WPR + 1];
    const int tid = threadIdx.x;
    const int b  = blockIdx.x >> 4;
    const int y0 = (blockIdx.x & 15) * RT;

    // load halo tile (rows y0-1 .. y0+RT)
    for (int k = tid; k < (RT + 2) * WPR; k += 256) {
        int r = k >> 4, w = k & (WPR - 1);
        int gy = y0 + r - 1;
        unsigned long long f = 0ull, s = 0ull;
        if ((unsigned)gy < (unsigned)H) {
            int o = (b * H + gy) * WPR + w;
            f = g_fill[o];
            s = g_strong[o];
        }
        sF[r][w] = f;
        sS[r][w] = s;
    }
    __syncthreads();

    int any = 0;
    for (;;) {
        int ch = 0;
#pragma unroll
        for (int m = 0; m < (RT * WPR) / 256; ++m) {
            int idx = tid + m * 256;
            int r = (idx >> 4) + 1;
            int w = idx & (WPR - 1);
            unsigned long long F = sF[r][w];
            unsigned long long cur = sS[r][w];
            if (F == cur) continue;   // nothing left to promote in this word
            unsigned long long d = 0ull;
#pragma unroll
            for (int dr = -1; dr <= 1; ++dr) {
                unsigned long long x = sS[r + dr][w];
                unsigned long long lft = (x << 1) | (w > 0 ? (sS[r + dr][w - 1] >> 63) : 0ull);
                unsigned long long rgt = (x >> 1) | (w < WPR - 1 ? (sS[r + dr][w + 1] << 63) : 0ull);
                d |= x | lft | rgt;
            }
            unsigned long long ns = (F & d) | cur;
            if (ns != cur) { sS[r][w] = ns; ch = 1; }
        }
        if (ch) any = 1;
        if (!__syncthreads_or(ch)) break;
    }

    if (__syncthreads_or(any)) {
        for (int k = tid; k < RT * WPR; k += 256) {
            int r = (k >> 4) + 1, w = k & (WPR - 1);
            g_strong[(b * H + y0 + r - 1) * WPR + w] = sS[r][w];
        }
        if (tid == 0) g_changed[pass] = 1;
    }
}

// =====================================================================
// Kernel C: edges = 1.0 where strong else 0.0
// =====================================================================
__global__ __launch_bounds__(256) void edges_final(float* __restrict__ e)
{
    int i = blockIdx.x * 256 + threadIdx.x;       // over NPIX/4
    unsigned wrd = ((const unsigned*)g_strong)[i >> 3];
    int sh = (i & 7) * 4;
    float4 f;
    f.x = (wrd >> (sh + 0)) & 1u ? 1.0f : 0.0f;
    f.y = (wrd >> (sh + 1)) & 1u ? 1.0f : 0.0f;
    f.z = (wrd >> (sh + 2)) & 1u ? 1.0f : 0.0f;
    f.w = (wrd >> (sh + 3)) & 1u ? 1.0f : 0.0f;
    ((float4*)e)[i] = f;
}

// =====================================================================
extern "C" void kernel_launch(void* const* d_in, const int* in_sizes, int n_in,
                              void* d_out, int out_size)
{
    (void)in_sizes; (void)n_in; (void)out_size;
    const float* x = (const float*)d_in[0];
    float* out = (float*)d_out;          // magnitude (4,1,1024,1024)
    float* edges = out + (size_t)NPIX;   // edges     (4,1,1024,1024)

    dim3 grid(32, 32, NB);
    canny_main<<<grid, 256>>>(x, out);

    for (int p = 0; p < NPASS; ++p)
        hyst_pass<<<HBLOCKS, 256>>>(p);

    edges_final<<<NPIX / 1024, 256>>>(edges);
}